// round 7
// baseline (speedup 1.0000x reference)
#include <cuda_runtime.h>
#include <cstdint>

#define NC      19
#define HW      (512 * 512)
#define NB      8
#define GX      32                  // blocks per image -> 256 blocks total
#define PXB     (HW / GX)           // 8192 pixels per block (exact)
#define THREADS 320
#define NWARP   10
#define NBINS   (NC * NC + NC)      // 380
#define NBLK    (NB * GX)           // 256

// Dynamic smem layout (floats):
//   acc   [NC][NC][32]  : 11552 floats (46,208 B)   bin (c,k), private lane column
//   cnt   [NC][32]      :   608 floats ( 2,432 B)
//   labels u8[PXB]      :  2048 u32    ( 8,192 B)
#define CNT_OFF  (NC * NC * 32)
#define LAB_OFF  (CNT_OFF + NC * 32)
#define SMEM_FLOATS (LAB_OFF + PXB / 4)          // 14,208 floats = 56,832 B

// Per-block partials, transposed for coalesced float4 reads in finalize.
__device__ __align__(16) float g_part[NB][NBINS][GX];
__device__ unsigned int g_count;                  // zero-init; reset by finalizer

__global__ __launch_bounds__(THREADS, 4)
void fused_kernel(const float* __restrict__ seg, const void* __restrict__ lab,
                  float* __restrict__ out) {
    extern __shared__ float sm[];
    float* acc = sm;
    float* cnt = sm + CNT_OFF;
    unsigned int* labw = (unsigned int*)(sm + LAB_OFF);

    const int tid  = threadIdx.x;
    const int lane = tid & 31;
    const int w    = tid >> 5;
    const int gx   = blockIdx.x;
    const int b    = blockIdx.y;

    // Zero accumulators (labels are fully overwritten below; no need to zero).
    for (int i = tid; i < LAB_OFF; i += THREADS) sm[i] = 0.0f;

    // Label dtype detect: odd 32-bit words of the first 32 labels are all zero <=> int64.
    int oddv = ((const int*)lab)[2 * lane + 1];
    bool is64 = (__ballot_sync(0xffffffffu, oddv != 0) == 0u);

    const long long pbase = (long long)b * HW + (long long)gx * PXB;

    // Stage labels for this block's 8192 pixels as packed u8 (4 per u32 word).
    if (is64) {
        const longlong2* L = (const longlong2*)((const long long*)lab + pbase);
        for (int wd = tid; wd < PXB / 4; wd += THREADS) {
            longlong2 a = __ldcs(L + 2 * wd);
            longlong2 c = __ldcs(L + 2 * wd + 1);
            labw[wd] = (unsigned)a.x | ((unsigned)a.y << 8) |
                       ((unsigned)c.x << 16) | ((unsigned)c.y << 24);
        }
    } else {
        const int4* L = (const int4*)((const int*)lab + pbase);
        for (int wd = tid; wd < PXB / 4; wd += THREADS) {
            int4 a = __ldcs(L + wd);
            labw[wd] = (unsigned)a.x | ((unsigned)a.y << 8) |
                       ((unsigned)a.z << 16) | ((unsigned)a.w << 24);
        }
    }
    __syncthreads();

    // Accumulate: warp w owns channels 2w, 2w+1 (warp 9: channel 18 + counts).
    // acc addr = ((c*19 + k)*32 + lane): bank == lane -> conflict-free, race-free.
    const int c0  = 2 * w;
    const int nch = (c0 + 1 < NC) ? 2 : ((c0 < NC) ? 1 : 0);
    for (int ci = 0; ci < nch; ci++) {
        const int c = c0 + ci;
        const float4* sp = (const float4*)(seg + ((size_t)b * NC + c) * HW +
                                           (size_t)gx * PXB);
        float* accc = acc + c * (NC * 32) + lane;
#pragma unroll 4
        for (int j = 0; j < PXB / 128; j++) {       // 64 iterations
            const int idx = j * 32 + lane;
            float4 v = __ldcs(sp + idx);            // 512B/warp contiguous
            unsigned pk = labw[idx];                // conflict-free u32 read
            accc[(pk & 0xffu) * 32]         += v.x;
            accc[((pk >> 8) & 0xffu) * 32]  += v.y;
            accc[((pk >> 16) & 0xffu) * 32] += v.z;
            accc[(pk >> 24) * 32]           += v.w;
        }
    }
    if (w == NWARP - 1) {                           // counts
        float* cl = cnt + lane;
#pragma unroll 4
        for (int j = 0; j < PXB / 128; j++) {
            unsigned pk = labw[j * 32 + lane];
            cl[(pk & 0xffu) * 32]         += 1.0f;
            cl[((pk >> 8) & 0xffu) * 32]  += 1.0f;
            cl[((pk >> 16) & 0xffu) * 32] += 1.0f;
            cl[(pk >> 24) * 32]           += 1.0f;
        }
    }
    __syncthreads();

    // Reduce 32 lane-columns per bin (rotation keeps intra-warp conflict-free).
    for (int bin = tid; bin < NBINS; bin += THREADS) {
        const float* col = (bin < NC * NC) ? (sm + bin * 32)
                                           : (sm + CNT_OFF + (bin - NC * NC) * 32);
        float s = 0.0f;
#pragma unroll
        for (int j = 0; j < 32; j++) s += col[(j + tid) & 31];
        g_part[b][bin][gx] = s;
    }

    // Last-block finalize handshake.
    __threadfence();
    __syncthreads();
    __shared__ unsigned int s_last;
    if (tid == 0) s_last = atomicAdd(&g_count, 1u);
    __syncthreads();
    if (s_last != NBLK - 1) return;
    __threadfence();

    // ---- Finalize (one block, 320 threads) ----
    // Sum partials: each thread owns whole (b,bin) rows -> 8 independent LDG.128 per row.
    float* sS = sm;   // reuse dynamic smem: [NB*NBINS] floats
    const float4* gp4 = (const float4*)&g_part[0][0][0];
    for (int pair = tid; pair < NB * NBINS; pair += THREADS) {
        float s = 0.0f;
#pragma unroll
        for (int j = 0; j < GX / 4; j++) {
            float4 v = __ldcg(gp4 + pair * (GX / 4) + j);
            s += (v.x + v.y) + (v.z + v.w);
        }
        sS[pair] = s;
    }
    __syncthreads();

    double local = 0.0;
    for (int t2 = tid; t2 < NC * NC; t2 += THREADS) {
        const int i = t2 / NC, k = t2 % NC;
#pragma unroll
        for (int bb = 0; bb < NB; bb++) {
            const float* r = sS + bb * NBINS;
            float ci_ = r[NC * NC + i], ck = r[NC * NC + k];
            float Sii = r[i * NC + i],  Sik = r[i * NC + k];
            double alpha = (ci_ > 0.0f) ? (double)Sii / (double)ci_ : 0.0;
            double beta  = (ck  > 0.0f) ? 1.0 - (double)Sik / (double)ck : 0.0;
            local += log(0.5 * (alpha + beta + 2.220446049250313e-16));
        }
    }
#pragma unroll
    for (int o = 16; o; o >>= 1)
        local += __shfl_down_sync(0xffffffffu, local, o);
    __shared__ double ws[NWARP];
    if (lane == 0) ws[w] = local;
    __syncthreads();
    if (tid == 0) {
        double tot = 0.0;
#pragma unroll
        for (int j = 0; j < NWARP; j++) tot += ws[j];
        out[0] = (float)(-0.5 * tot / (double)NB);
        g_count = 0u;                               // reset for next graph replay
    }
}

extern "C" void kernel_launch(void* const* d_in, const int* in_sizes, int n_in,
                              void* d_out, int out_size) {
    const float* seg = (const float*)d_in[0];
    const void*  lab = d_in[1];
    float* out = (float*)d_out;

    const int smem = SMEM_FLOATS * sizeof(float);   // 56,832 B
    (void)cudaFuncSetAttribute(fused_kernel,
                               cudaFuncAttributeMaxDynamicSharedMemorySize, smem);

    dim3 grid(GX, NB);
    fused_kernel<<<grid, THREADS, smem>>>(seg, lab, out);
}